// round 14
// baseline (speedup 1.0000x reference)
#include <cuda_runtime.h>
#include <math.h>

#define N_NODE 200
#define N_HID  1500
#define N_BAT  20
#define N_IN   6
#define NTH    320          // 10 warps; each warp owns 20 rows (10 row-pairs)

// ---------------- scratch (static device globals; no allocation) ----------------
__device__ float g_wl[N_NODE * N_NODE];
__device__ float g_rowsum[N_NODE];
__device__ float g_part[N_NODE];
__device__ float g_ls[N_NODE * N_NODE];
// transposed noise: [hb = h*20+b][node][2]
__device__ float g_noise[(size_t)N_HID * N_BAT * N_NODE * 2];

// ---------------- prep1: w_l rows + row sums + sq-norm partials ----------------
__global__ void prep1_kernel(const float* __restrict__ sc, const float* __restrict__ wbb) {
    int r = blockIdx.x;
    int c = threadIdx.x;
    float wl = 0.f;
    if (c < N_NODE) {
        float w_rc = expf(wbb[r * N_NODE + c]) * sc[r * N_NODE + c];
        float w_cr = expf(wbb[c * N_NODE + r]) * sc[c * N_NODE + r];
        wl = log1pf(0.5f * (w_rc + w_cr));
        g_wl[r * N_NODE + c] = wl;
    }
    __shared__ float s1[256], s2[256];
    s1[threadIdx.x] = wl;
    s2[threadIdx.x] = wl * wl;
    __syncthreads();
    for (int s = 128; s > 0; s >>= 1) {
        if (threadIdx.x < s) {
            s1[threadIdx.x] += s1[threadIdx.x + s];
            s2[threadIdx.x] += s2[threadIdx.x + s];
        }
        __syncthreads();
    }
    if (threadIdx.x == 0) {
        g_rowsum[r] = s1[0];
        g_part[r]   = s2[0];
    }
}

// ---------------- prep23: per-block redundant norm + build l_s ----------------
__global__ void prep23_kernel() {
    __shared__ float s[256];
    int t = threadIdx.x;
    s[t] = (t < N_NODE) ? g_part[t] : 0.f;
    __syncthreads();
    for (int k = 128; k > 0; k >>= 1) {
        if (t < k) s[t] += s[t + k];
        __syncthreads();
    }
    float invnorm = 1.f / sqrtf(s[0]);   // identical in every block (deterministic)
    int r = blockIdx.x;
    if (t < N_NODE) {
        float v = g_wl[r * N_NODE + t];
        if (t == r) v -= g_rowsum[r];
        g_ls[r * N_NODE + t] = v * invnorm;
    }
}

// ---------------- noise transpose: ext(node,h,b,k) -> g_noise(hb,node,2) ----------
__global__ void transpose_noise_kernel(const float* __restrict__ ext) {
    __shared__ float2 tile[32][33];
    int hb0 = blockIdx.x * 32;
    int n0  = blockIdx.y * 32;
    for (int yy = threadIdx.y; yy < 32; yy += 8) {
        int node = n0 + yy;
        int hb   = hb0 + threadIdx.x;
        float2 v = make_float2(0.f, 0.f);
        if (node < N_NODE && hb < N_HID * N_BAT) {
            const float* s = ext + ((size_t)node * (N_HID * N_BAT) + hb) * N_IN;
            v.x = s[0]; v.y = s[1];
        }
        tile[yy][threadIdx.x] = v;
    }
    __syncthreads();
    for (int yy = threadIdx.y; yy < 32; yy += 8) {
        int hb   = hb0 + yy;
        int node = n0 + threadIdx.x;
        if (node < N_NODE && hb < N_HID * N_BAT) {
            *(float2*)&g_noise[((size_t)hb * N_NODE + node) * 2] = tile[threadIdx.x][yy];
        }
    }
}

// ---------------- simulation helpers ----------------
__device__ __forceinline__ float h_tf_dev(float a, float b, float d, float z) {
    float u   = fmaf(a, z, -b);
    float num = 1e-5f + fabsf(u);
    float den = fmaf(1e-5f, d, fabsf(1.0f - __expf(-d * u)));
    return __fdividef(num, den);
}

__device__ __forceinline__ float tanh_hw(float y) {
    float r;
    asm("tanh.approx.f32 %0, %1;" : "=f"(r) : "f"(y));
    return r;
}

#define FMA2(acc, a, b) \
    asm("fma.rn.f32x2 %0, %1, %2, %0;" : "+l"(acc) : "l"(a), "l"(b))

__global__ void __launch_bounds__(NTH, 1) sim_kernel(
    const float* __restrict__ ext,   // original layout — only for BOLD n2
    const float* __restrict__ hx,    // (200,6)
    float* __restrict__ out,         // (200,20)
    const float* gp, const float* gEEp, const float* gIEp,
    const float* gEIp, const float* stdp)
{
    __shared__ __align__(16) float Ebuf[2][224];       // E padded to 224, pads = 0
    __shared__ __align__(16) float AccW[10 * 8 * 20];  // [warp][class(8)][row(20)]

    const int tid  = threadIdx.x;
    const int w    = tid >> 5;
    const int l    = tid & 31;
    const int rbase = w * 20;                 // rows 20w..20w+19 (this warp)
    const bool act = (l < 20);
    const int node = rbase + (act ? l : 0);   // lanes 20-31 shadow node rbase

    // ---- W registers: exactly 10 row-pairs, 7 interleaved cols/lane (pad->0) ----
    unsigned long long W2[10][7];
#pragma unroll
    for (int jp = 0; jp < 10; jp++) {
        int r0 = rbase + 2 * jp;
#pragma unroll
        for (int j = 0; j < 7; j++) {
            int col = l + 32 * j;
            float w0 = (col < N_NODE) ? g_ls[r0 * N_NODE + col] : 0.f;
            float w1 = (col < N_NODE) ? g_ls[(r0 + 1) * N_NODE + col] : 0.f;
            asm("mov.b64 %0, {%1, %2};" : "=l"(W2[jp][j]) : "f"(w0), "f"(w1));
        }
    }

    const float gg   = *gp;
    const float cEE  = 0.001f + fmaxf(*gEEp, 0.f);
    const float cIE  = 0.001f + fmaxf(*gIEp, 0.f);
    const float cEI  = 0.001f + fmaxf(*gEIp, 0.f);
    const float nscl = 0.70710678118654752440f * (0.02f + fmaxf(*stdp, 0.f));

    float E = 0.f, I = 0.f, X = 0.f, F = 0.f, V = 0.f, Q = 0.f, vpow = 0.f;

    for (int i = tid; i < 2 * 224; i += NTH) ((float*)Ebuf)[i] = 0.f;
    __syncthreads();

    if (act) {
        E = hx[node * 6 + 0];
        I = hx[node * 6 + 1];
        X = hx[node * 6 + 2];
        F = hx[node * 6 + 3];
        V = hx[node * 6 + 4];
        Q = hx[node * 6 + 5];
        vpow = __expf(3.125f * __logf(V));
        Ebuf[0][node] = E;
    }
    __syncthreads();

    // warp-private Acc region: [class][row], class stride 20
    // bank check: 20*l mod 32 for l<8 = {0,20,8,28,16,4,24,12} — all distinct.
    float* accw = &AccW[w * 160];

    float* curE = Ebuf[0];
    float* nxtE = Ebuf[1];

#pragma unroll 1
    for (int b = 0; b < N_BAT; b++) {
        const float* np = g_noise + ((size_t)b * N_NODE + node) * 2;
#pragma unroll 1
        for (int h = 0; h < N_HID; h++) {
            // ---- noise for this step: issue first; g_noise is L2-resident
            //      (48MB, written once, streamed) so latency < matvec window ----
            float nx = 0.f, ny = 0.f;
            if (act) {
                float2 t0 = *(const float2*)np;
                nx = t0.x; ny = t0.y;
            }
            np += (size_t)N_BAT * N_NODE * 2;

            // -------- phase A: column-interleaved matvec (10 row-pairs) --------
            unsigned long long ed[7];
#pragma unroll
            for (int j = 0; j < 7; j++) {
                float e = curE[l + 32 * j];
                asm("mov.b64 %0, {%1, %1};" : "=l"(ed[j]) : "f"(e));
            }

            float p[20];
#pragma unroll
            for (int jp = 0; jp < 10; jp++) {
                unsigned long long acc = 0ull;
#pragma unroll
                for (int j = 0; j < 7; j++) FMA2(acc, W2[jp][j], ed[j]);
                asm("mov.b64 {%0, %1}, %2;" : "=f"(p[2 * jp]), "=f"(p[2 * jp + 1]) : "l"(acc));
            }

            // ---- two butterflies -> lanes 0-7 hold 8 col-class partials -------
#pragma unroll
            for (int i = 0; i < 20; i++)
                p[i] += __shfl_xor_sync(0xffffffffu, p[i], 16);
#pragma unroll
            for (int i = 0; i < 20; i++)
                p[i] += __shfl_xor_sync(0xffffffffu, p[i], 8);

            if (l < 8) {               // publish to warp-private region
                float* ap = accw + l * 20;
#pragma unroll
                for (int jp = 0; jp < 10; jp++)
                    *(float2*)&ap[2 * jp] = make_float2(p[2 * jp], p[2 * jp + 1]);
            }
            __syncwarp(0xffffffffu);   // warp-local handoff

            // -------- phase B: each lane updates its own node -------------------
            if (act) {
                float a0 = accw[0 * 20 + l] + accw[1 * 20 + l];
                float a1 = accw[2 * 20 + l] + accw[3 * 20 + l];
                float a2 = accw[4 * 20 + l] + accw[5 * 20 + l];
                float a3 = accw[6 * 20 + l] + accw[7 * 20 + l];
                float acc = gg * ((a0 + a1) + (a2 + a3));

                float Eold = E, Iold = I;
                float IE = fmaxf(acc + fmaf(cEE, Eold, 0.32f) - cIE * Iold, 0.f);
                float II = fmaxf(fmaf(cEI, Eold, 0.224f) - Iold, 0.f);
                float rE = h_tf_dev(310.f, 125.f, 0.16f,  IE);
                float rI = h_tf_dev(615.f, 177.f, 0.087f, II);
                float En = Eold + 0.5f * fmaf(0.000641f * (1.f - Eold), rE, -0.01f * Eold)
                                + nscl * nx;
                float In = Iold + 0.5f * fmaf(0.001f, rI, -0.1f * Iold)
                                + nscl * ny;
                E = tanh_hw(1e-5f + fmaxf(En, 0.f));
                I = tanh_hw(1e-5f + fmaxf(In, 0.f));
                nxtE[node] = E;

                // deferred hemodynamics for step h-1 (uses Eold; ILP-overlaps E/I)
                if (h > 0) {
                    X = X + 0.5f * (Eold - X * (1.f / 0.65f) - (F - 1.f) * (1.f / 0.41f));
                    F = F + 0.5f * X;
                    float Vn = fmaf(0.5f / 0.98f, F - vpow, V);
                    float vq = __expf(3.125f * __logf(Vn));
                    float qa = F * (1.f - __expf(__fdividef(-0.41551544396166582194f, F)))
                                 * (1.f / 0.34f);
                    float qb = __fdividef(Q * vq, Vn);
                    Q = fmaf(0.5f / 0.98f, qa - qb, Q);
                    V = Vn; vpow = vq;
                }
            }
            __syncthreads();           // ONE block barrier per step: nxtE ready
            float* t2 = curE; curE = nxtE; nxtE = t2;
        }

        // -------- batch end: flush lagging hemo + emit BOLD --------------------
        if (act) {
            float Eold = E;
            X = X + 0.5f * (Eold - X * (1.f / 0.65f) - (F - 1.f) * (1.f / 0.41f));
            F = F + 0.5f * X;
            float Vn = fmaf(0.5f / 0.98f, F - vpow, V);
            float vq = __expf(3.125f * __logf(Vn));
            float qa = F * (1.f - __expf(__fdividef(-0.41551544396166582194f, F)))
                         * (1.f / 0.34f);
            float qb = __fdividef(Q * vq, Vn);
            Q = fmaf(0.5f / 0.98f, qa - qb, Q);
            V = Vn; vpow = vq;

            float n2 = ext[((size_t)(node * N_HID + (N_HID - 1)) * N_BAT + b) * N_IN + 2];
            float bold = 0.02f * n2 +
                5.8823529411764705882f * (2.38f * (1.f - Q)
                                        + 2.f * (1.f - __fdividef(Q, V))
                                        + 0.48f * (1.f - V));
            out[node * N_BAT + b] = bold;
        }
    }
}

// ---------------- launch (exactly 4 kernels) ----------------
extern "C" void kernel_launch(void* const* d_in, const int* in_sizes, int n_in,
                              void* d_out, int out_size) {
    const float* ext  = (const float*)d_in[0];  // external (200,1500,20,6)
    const float* hx   = (const float*)d_in[1];  // hx (200,6)
    // d_in[2] = hE (unused by reference)
    const float* sc   = (const float*)d_in[3];  // sc (200,200)
    const float* wbb  = (const float*)d_in[4];  // w_bb (200,200)
    const float* gp   = (const float*)d_in[5];
    const float* gEE  = (const float*)d_in[6];
    const float* gIE  = (const float*)d_in[7];
    const float* gEI  = (const float*)d_in[8];
    const float* stdp = (const float*)d_in[9];
    float* out = (float*)d_out;

    prep1_kernel<<<N_NODE, 256>>>(sc, wbb);
    prep23_kernel<<<N_NODE, 256>>>();
    {
        dim3 grid((N_HID * N_BAT + 31) / 32, (N_NODE + 31) / 32);
        dim3 blk(32, 8);
        transpose_noise_kernel<<<grid, blk>>>(ext);
    }
    sim_kernel<<<1, NTH>>>(ext, hx, out, gp, gEE, gIE, gEI, stdp);
}

// round 15
// speedup vs baseline: 1.6078x; 1.6078x over previous
#include <cuda_runtime.h>
#include <math.h>

#define N_NODE 200
#define N_HID  1500
#define N_BAT  20
#define N_IN   6
#define NTH    256          // 8 warps x 32; warp owns 25 rows; lane<25 owns a node

// ---------------- scratch (static device globals; no allocation) ----------------
__device__ float g_wl[N_NODE * N_NODE];
__device__ float g_rowsum[N_NODE];
__device__ float g_part[N_NODE];
__device__ float g_ls[N_NODE * N_NODE];
// transposed noise: [hb = h*20+b][node][2]
__device__ float g_noise[(size_t)N_HID * N_BAT * N_NODE * 2];

// ---------------- prep1: w_l rows + row sums + sq-norm partials ----------------
__global__ void prep1_kernel(const float* __restrict__ sc, const float* __restrict__ wbb) {
    int r = blockIdx.x;
    int c = threadIdx.x;
    float wl = 0.f;
    if (c < N_NODE) {
        float w_rc = expf(wbb[r * N_NODE + c]) * sc[r * N_NODE + c];
        float w_cr = expf(wbb[c * N_NODE + r]) * sc[c * N_NODE + r];
        wl = log1pf(0.5f * (w_rc + w_cr));
        g_wl[r * N_NODE + c] = wl;
    }
    __shared__ float s1[256], s2[256];
    s1[threadIdx.x] = wl;
    s2[threadIdx.x] = wl * wl;
    __syncthreads();
    for (int s = 128; s > 0; s >>= 1) {
        if (threadIdx.x < s) {
            s1[threadIdx.x] += s1[threadIdx.x + s];
            s2[threadIdx.x] += s2[threadIdx.x + s];
        }
        __syncthreads();
    }
    if (threadIdx.x == 0) {
        g_rowsum[r] = s1[0];
        g_part[r]   = s2[0];
    }
}

// ---------------- prep23: per-block redundant norm + build l_s ----------------
__global__ void prep23_kernel() {
    __shared__ float s[256];
    int t = threadIdx.x;
    s[t] = (t < N_NODE) ? g_part[t] : 0.f;
    __syncthreads();
    for (int k = 128; k > 0; k >>= 1) {
        if (t < k) s[t] += s[t + k];
        __syncthreads();
    }
    float invnorm = 1.f / sqrtf(s[0]);   // identical in every block (deterministic)
    int r = blockIdx.x;
    if (t < N_NODE) {
        float v = g_wl[r * N_NODE + t];
        if (t == r) v -= g_rowsum[r];
        g_ls[r * N_NODE + t] = v * invnorm;
    }
}

// ---------------- noise transpose: ext(node,h,b,k) -> g_noise(hb,node,2) ----------
__global__ void transpose_noise_kernel(const float* __restrict__ ext) {
    __shared__ float2 tile[32][33];
    int hb0 = blockIdx.x * 32;
    int n0  = blockIdx.y * 32;
    for (int yy = threadIdx.y; yy < 32; yy += 8) {
        int node = n0 + yy;
        int hb   = hb0 + threadIdx.x;
        float2 v = make_float2(0.f, 0.f);
        if (node < N_NODE && hb < N_HID * N_BAT) {
            const float* s = ext + ((size_t)node * (N_HID * N_BAT) + hb) * N_IN;
            v.x = s[0]; v.y = s[1];
        }
        tile[yy][threadIdx.x] = v;
    }
    __syncthreads();
    for (int yy = threadIdx.y; yy < 32; yy += 8) {
        int hb   = hb0 + yy;
        int node = n0 + threadIdx.x;
        if (node < N_NODE && hb < N_HID * N_BAT) {
            *(float2*)&g_noise[((size_t)hb * N_NODE + node) * 2] = tile[threadIdx.x][yy];
        }
    }
}

// ---------------- fast math helpers ----------------
__device__ __forceinline__ float ex2f(float x){ float r; asm("ex2.approx.f32 %0, %1;" : "=f"(r) : "f"(x)); return r; }
__device__ __forceinline__ float lg2f(float x){ float r; asm("lg2.approx.f32 %0, %1;" : "=f"(r) : "f"(x)); return r; }
__device__ __forceinline__ float rcpf(float x){ float r; asm("rcp.approx.f32 %0, %1;" : "=f"(r) : "f"(x)); return r; }
__device__ __forceinline__ float tanh_hw(float y){ float r; asm("tanh.approx.f32 %0, %1;" : "=f"(r) : "f"(y)); return r; }

#define FMA2(acc, a, b) \
    asm("fma.rn.f32x2 %0, %1, %2, %0;" : "+l"(acc) : "l"(a), "l"(b))

// h_tf with pre-folded exp argument: t = 2^(c1*z + c2) = exp(-d*(a*z-b))
// num = 1e-5 + |a*z-b| ; den = 1e-5*d + |1-t| ; returns num/den
__device__ __forceinline__ float h_tf_fast(float a, float b, float dd5,
                                           float c1, float c2, float z) {
    float u  = fmaf(a, z, -b);                  // parallel with xa
    float xa = fmaf(c1, z, c2);                 // -d*log2e*(a*z-b)
    float t  = ex2f(xa);
    float num = 1e-5f + fabsf(u);
    float den = dd5 + fabsf(1.0f - t);
    return num * rcpf(den);
}

// shared hemodynamics step (one reference step, given the E that drove it)
#define HEMO(Eold)                                                             \
    do {                                                                       \
        X = X + 0.5f * ((Eold) - X * (1.f / 0.65f) - (F - 1.f) * (1.f / 0.41f)); \
        F = F + 0.5f * X;                                                      \
        float Vn = fmaf(0.5f / 0.98f, F - vpow, V);                            \
        float vq = ex2f(3.125f * lg2f(Vn));                                    \
        float qa = F * (1.f - ex2f(-0.59946207f * rcpf(F))) * (1.f / 0.34f);   \
        float qb = Q * vq * rcpf(Vn);                                          \
        Q = fmaf(0.5f / 0.98f, qa - qb, Q);                                    \
        V = Vn; vpow = vq;                                                     \
    } while (0)

__global__ void __launch_bounds__(NTH, 1) sim_kernel(
    const float* __restrict__ ext,   // original layout — only for BOLD n2
    const float* __restrict__ hx,    // (200,6)
    float* __restrict__ out,         // (200,20)
    const float* gp, const float* gEEp, const float* gIEp,
    const float* gEIp, const float* stdp)
{
    __shared__ __align__(16) float Ebuf[2][224];      // E padded to 224, pads = 0
    __shared__ __align__(16) float AccW[8 * 16 * 25]; // [warp][class(16)][row(25)]

    const int tid  = threadIdx.x;
    const int w    = tid >> 5;
    const int l    = tid & 31;
    const int rbase = w * 25;                  // rows 25w..25w+24 (this warp)
    const bool act = (l < 25);
    const int node = rbase + (act ? l : 0);    // lanes 25-31 shadow node rbase

    // ---- W registers: 12 row-pairs + 1 single row, 7 interleaved cols/lane ----
    unsigned long long W2[12][7];
    float Ws[7];
#pragma unroll
    for (int jp = 0; jp < 12; jp++) {
        int r0 = rbase + 2 * jp;
#pragma unroll
        for (int j = 0; j < 7; j++) {
            int col = l + 32 * j;
            float w0 = (col < N_NODE) ? g_ls[r0 * N_NODE + col] : 0.f;
            float w1 = (col < N_NODE) ? g_ls[(r0 + 1) * N_NODE + col] : 0.f;
            asm("mov.b64 %0, {%1, %2};" : "=l"(W2[jp][j]) : "f"(w0), "f"(w1));
        }
    }
#pragma unroll
    for (int j = 0; j < 7; j++) {
        int col = l + 32 * j;
        Ws[j] = (col < N_NODE) ? g_ls[(rbase + 24) * N_NODE + col] : 0.f;
    }

    const float gg   = *gp;
    const float cEE  = 0.001f + fmaxf(*gEEp, 0.f);
    const float cIE  = 0.001f + fmaxf(*gIEp, 0.f);
    const float cEI  = 0.001f + fmaxf(*gEIp, 0.f);
    const float nscl = 0.70710678118654752440f * (0.02f + fmaxf(*stdp, 0.f));

    // h_tf folded exp-arg constants: c1 = -d*a*log2e, c2 = d*b*log2e
    const float c1E = -71.557673722f;   // -0.16*310*log2e
    const float c2E =  28.853900817f;   //  0.16*125*log2e
    const float c1I = -77.191394861f;   // -0.087*615*log2e
    const float c2I =  22.216064906f;   //  0.087*177*log2e

    float E = 0.f, I = 0.f, X = 0.f, F = 0.f, V = 0.f, Q = 0.f, vpow = 0.f;

    for (int i = tid; i < 2 * 224; i += NTH) ((float*)Ebuf)[i] = 0.f;
    __syncthreads();

    if (act) {
        E = hx[node * 6 + 0];
        I = hx[node * 6 + 1];
        X = hx[node * 6 + 2];
        F = hx[node * 6 + 3];
        V = hx[node * 6 + 4];
        Q = hx[node * 6 + 5];
        vpow = ex2f(3.125f * lg2f(V));
        Ebuf[0][node] = E;
    }
    __syncthreads();

    // warp-private Acc region: [class(16)][row(25)], class stride 25.
    // publish banks: (25c + r) mod 32 distinct for c<16 (25 odd); the +13-row
    // half from lanes 16-31 is bank-disjoint (c1 = c2+21 unsatisfiable). 1 phase.
    float* accw = &AccW[w * 400];
    const bool lowhalf = (l < 16);
    float* ap0 = accw + (l & 15) * 25 + (lowhalf ? 0 : 13);

    float* curE = Ebuf[0];
    float* nxtE = Ebuf[1];

#pragma unroll 1
    for (int b = 0; b < N_BAT; b++) {
        const float* np = g_noise + ((size_t)b * N_NODE + node) * 2;
#pragma unroll 1
        for (int h = 0; h < N_HID; h++) {
            // ---- noise for this step: issued first; L2-resident, covered -----
            float nx = 0.f, ny = 0.f;
            if (act) {
                float2 t0 = *(const float2*)np;
                nx = t0.x; ny = t0.y;
            }
            np += (size_t)N_BAT * N_NODE * 2;

            // -------- phase A: column-interleaved matvec ----------------------
            float e[7];
#pragma unroll
            for (int j = 0; j < 7; j++) e[j] = curE[l + 32 * j];
            unsigned long long ed[7];
#pragma unroll
            for (int j = 0; j < 7; j++)
                asm("mov.b64 %0, {%1, %1};" : "=l"(ed[j]) : "f"(e[j]));

            float p[25];
#pragma unroll
            for (int jp = 0; jp < 12; jp++) {
                unsigned long long acc = 0ull;
#pragma unroll
                for (int j = 0; j < 7; j++) FMA2(acc, W2[jp][j], ed[j]);
                asm("mov.b64 {%0, %1}, %2;" : "=f"(p[2 * jp]), "=f"(p[2 * jp + 1]) : "l"(acc));
            }
            {
                float ps = 0.f;
#pragma unroll
                for (int j = 0; j < 7; j++) ps = fmaf(Ws[j], e[j], ps);
                p[24] = ps;
            }

            // ---- ONE butterfly stage -> all lanes hold 16-col-class partials --
#pragma unroll
            for (int i = 0; i < 25; i++)
                p[i] += __shfl_xor_sync(0xffffffffu, p[i], 16);

            // ---- publish: both halves store (rows 0-12 / 13-24), 13 STS ------
#pragma unroll
            for (int r = 0; r < 12; r++) {
                float v = lowhalf ? p[r] : p[r + 13];
                ap0[r] = v;
            }
            if (lowhalf) accw[(l & 15) * 25 + 12] = p[12];
            __syncwarp(0xffffffffu);

            // -------- phase B: each active lane updates its own node ----------
            if (act) {
                float a0, a1, a2, a3;
                a0  = accw[ 0 * 25 + l] + accw[ 1 * 25 + l];
                a1  = accw[ 2 * 25 + l] + accw[ 3 * 25 + l];
                a2  = accw[ 4 * 25 + l] + accw[ 5 * 25 + l];
                a3  = accw[ 6 * 25 + l] + accw[ 7 * 25 + l];
                a0 += accw[ 8 * 25 + l] + accw[ 9 * 25 + l];
                a1 += accw[10 * 25 + l] + accw[11 * 25 + l];
                a2 += accw[12 * 25 + l] + accw[13 * 25 + l];
                a3 += accw[14 * 25 + l] + accw[15 * 25 + l];
                float dot = (a0 + a1) + (a2 + a3);

                float Eold = E, Iold = I;
                // precomputable (parallel with the LDS/sum tree):
                float preE  = fmaf(cEE, Eold, 0.32f) - cIE * Iold;
                float coefE = fmaf(-0.0003205f, Eold, 0.0003205f); // 0.5*gammaE*(1-E)
                float baseE = fmaf(nscl, nx, 0.995f * Eold);
                float baseI = fmaf(nscl, ny, 0.95f * Iold);

                float IE = fmaxf(fmaf(gg, dot, preE), 0.f);
                float II = fmaxf(fmaf(cEI, Eold, 0.224f) - Iold, 0.f);
                float rE = h_tf_fast(310.f, 125.f, 1.6e-6f, c1E, c2E, IE);
                float rI = h_tf_fast(615.f, 177.f, 8.7e-7f, c1I, c2I, II);
                float En = fmaf(coefE, rE, baseE);
                float In = fmaf(0.0005f, rI, baseI);
                E = tanh_hw(1e-5f + fmaxf(En, 0.f));
                I = tanh_hw(1e-5f + fmaxf(In, 0.f));
                nxtE[node] = E;

                // deferred hemodynamics for step h-1 (uses Eold; ILP-overlaps)
                if (h > 0) HEMO(Eold);
            }
            __syncthreads();           // ONE block barrier per step: nxtE ready
            float* t2 = curE; curE = nxtE; nxtE = t2;
        }

        // -------- batch end: flush lagging hemo + emit BOLD --------------------
        if (act) {
            float Eold = E;
            HEMO(Eold);
            float n2 = ext[((size_t)(node * N_HID + (N_HID - 1)) * N_BAT + b) * N_IN + 2];
            float bold = 0.02f * n2 +
                5.8823529411764705882f * (2.38f * (1.f - Q)
                                        + 2.f * (1.f - Q * rcpf(V))
                                        + 0.48f * (1.f - V));
            out[node * N_BAT + b] = bold;
        }
    }
}

// ---------------- launch (exactly 4 kernels) ----------------
extern "C" void kernel_launch(void* const* d_in, const int* in_sizes, int n_in,
                              void* d_out, int out_size) {
    const float* ext  = (const float*)d_in[0];  // external (200,1500,20,6)
    const float* hx   = (const float*)d_in[1];  // hx (200,6)
    // d_in[2] = hE (unused by reference)
    const float* sc   = (const float*)d_in[3];  // sc (200,200)
    const float* wbb  = (const float*)d_in[4];  // w_bb (200,200)
    const float* gp   = (const float*)d_in[5];
    const float* gEE  = (const float*)d_in[6];
    const float* gIE  = (const float*)d_in[7];
    const float* gEI  = (const float*)d_in[8];
    const float* stdp = (const float*)d_in[9];
    float* out = (float*)d_out;

    prep1_kernel<<<N_NODE, 256>>>(sc, wbb);
    prep23_kernel<<<N_NODE, 256>>>();
    {
        dim3 grid((N_HID * N_BAT + 31) / 32, (N_NODE + 31) / 32);
        dim3 blk(32, 8);
        transpose_noise_kernel<<<grid, blk>>>(ext);
    }
    sim_kernel<<<1, NTH>>>(ext, hx, out, gp, gEE, gIE, gEI, stdp);
}